// round 3
// baseline (speedup 1.0000x reference)
#include <cuda_runtime.h>
#include <cuda_bf16.h>
#include <math.h>

// ---------------- problem constants ----------------
#define EMB   620
#define ECH   1000
#define A2    2000      // 2*ECH
#define H     1000      // DCH
#define V     30000
#define S     50
#define T     50
#define B     32
#define KX    3620      // EMB + H + A2
#define NSTEP (T-1)     // 49
#define NPRED (NSTEP*B) // 1568

#define PRED_ELEMS  ((size_t)T*B*V)       // 48,000,000
#define HID_OFF     PRED_ELEMS
#define ATT_OFF     (PRED_ELEMS + (size_t)B*H)

// ---------------- device scratch (static, no allocation) ----------------
__device__ float g_WhT[ECH * H];            // [k=1000][m=1000]
__device__ float g_WcT[(H + A2) * H];       // [k=3000][m=1000]
__device__ float g_WpT[(size_t)KX * V];     // [k=3620][m=30000]
__device__ float g_WgT[(size_t)KX * 4000];  // [k=3620][row=4000]
__device__ float g_bg[4000];
__device__ float g_annproj[S * B * H];      // [s*32+b][j]
__device__ float g_h[2][B * H];
__device__ float g_hproj[B * H];
__device__ float g_attn[S * B];
__device__ float g_X[(size_t)NSTEP * B * KX];
__device__ float g_gates[B * 4000];         // [b][row]

// ---------------- generic transpose: out[c*R + r] = in[r*C + c] ----------------
__global__ void transpose_kernel(const float* __restrict__ in, float* __restrict__ out,
                                 int R, int C) {
    __shared__ float tile[32][33];
    int c0 = blockIdx.x * 32, r0 = blockIdx.y * 32;
    int tx = threadIdx.x, ty = threadIdx.y;   // (32, 8)
    #pragma unroll
    for (int i = 0; i < 32; i += 8) {
        int r = r0 + ty + i, c = c0 + tx;
        tile[ty + i][tx] = (r < R && c < C) ? in[(size_t)r * C + c] : 0.f;
    }
    __syncthreads();
    #pragma unroll
    for (int i = 0; i < 32; i += 8) {
        int c = c0 + ty + i, r = r0 + tx;
        if (r < R && c < C) out[(size_t)c * R + r] = tile[tx][ty + i];
    }
}

// ---------------- build fused GRU weight (transposed) + bias ----------------
// rows 0..999   : r gate  (W_ih rows 0..999 fused with W_hh rows 0..999)
// rows 1000..1999: z gate (W_ih rows 1000.. fused with W_hh rows 1000..)
// rows 2000..2999: inn    (W_ih rows 2000.., zero on h-columns)
// rows 3000..3999: hn     (W_hh rows 2000.., zero elsewhere)
// column layout matches X = [emb(620), h(1000), ctx(2000)]
__global__ void build_wg_kernel(const float* __restrict__ W_ih,
                                const float* __restrict__ W_hh,
                                float* __restrict__ WgT) {
    size_t idx = (size_t)blockIdx.x * blockDim.x + threadIdx.x;
    size_t total = (size_t)KX * 4000;
    if (idx >= total) return;
    int row = (int)(idx % 4000);
    int k   = (int)(idx / 4000);
    float v = 0.f;
    if (row < 2000) {
        if (k < EMB)              v = W_ih[(size_t)row * 2620 + k];
        else if (k < EMB + H)     v = W_hh[(size_t)row * H + (k - EMB)];
        else                      v = W_ih[(size_t)row * 2620 + (k - H)];
    } else if (row < 3000) {
        if (k < EMB)              v = W_ih[(size_t)row * 2620 + k];
        else if (k >= EMB + H)    v = W_ih[(size_t)row * 2620 + (k - H)];
    } else {
        if (k >= EMB && k < EMB + H) v = W_hh[(size_t)(row - 1000) * H + (k - EMB)];
    }
    WgT[(size_t)k * 4000 + row] = v;
}

__global__ void build_bg_kernel(const float* __restrict__ b_ih,
                                const float* __restrict__ b_hh,
                                float* __restrict__ bg) {
    int r = blockIdx.x * blockDim.x + threadIdx.x;
    if (r >= 4000) return;
    float v;
    if (r < 2000)      v = b_ih[r] + b_hh[r];
    else if (r < 3000) v = b_ih[r];
    else               v = b_hh[r - 1000];
    bg[r] = v;
}

// ---------------- generic tiled GEMM ----------------
// C[m*cm + n*cn] = act( sum_k AT[k*ldA + m] * X[n*ldX + k] + bias[m] )
// BM=64, BN=32, BK=32, 128 threads, 4x4 microtile.
__global__ void __launch_bounds__(128)
gemm_kernel(const float* __restrict__ AT, const float* __restrict__ Xp,
            const float* __restrict__ bias, float* __restrict__ C,
            long long cm, long long cn, int M, int N, int K,
            int ldA, int ldX, int act) {
    __shared__ float Ws[32][64];
    __shared__ float Xs[32][33];
    int bm = blockIdx.x * 64, bn = blockIdx.y * 32;
    int tid = threadIdx.x;
    int tm = tid >> 3;          // 0..15 -> m = bm + tm*4
    int tn = tid & 7;           // 0..7  -> n = bn + tn*4
    float acc[4][4];
    #pragma unroll
    for (int i = 0; i < 4; i++)
        #pragma unroll
        for (int j = 0; j < 4; j++) acc[i][j] = 0.f;

    int a_m  = tid & 63;        // 0..63
    int a_k0 = tid >> 6;        // 0..1
    int x_k  = tid & 31;        // 0..31
    int x_n0 = tid >> 5;        // 0..3

    for (int k0 = 0; k0 < K; k0 += 32) {
        // A tile: Ws[kk][mm] = AT[(k0+kk)*ldA + bm+mm]
        #pragma unroll
        for (int p = 0; p < 16; p++) {
            int kk = p * 2 + a_k0;
            int m  = bm + a_m;
            int kg = k0 + kk;
            Ws[kk][a_m] = (kg < K && m < M) ? AT[(size_t)kg * ldA + m] : 0.f;
        }
        // X tile: Xs[kk][nn] = X[(bn+nn)*ldX + k0+kk]
        #pragma unroll
        for (int p = 0; p < 8; p++) {
            int nn = p * 4 + x_n0;
            int n  = bn + nn;
            int kg = k0 + x_k;
            Xs[x_k][nn] = (n < N && kg < K) ? Xp[(size_t)n * ldX + kg] : 0.f;
        }
        __syncthreads();
        #pragma unroll
        for (int kk = 0; kk < 32; kk++) {
            float4 wv = *reinterpret_cast<const float4*>(&Ws[kk][tm * 4]);
            float x0 = Xs[kk][tn * 4 + 0];
            float x1 = Xs[kk][tn * 4 + 1];
            float x2 = Xs[kk][tn * 4 + 2];
            float x3 = Xs[kk][tn * 4 + 3];
            acc[0][0] += wv.x * x0; acc[0][1] += wv.x * x1; acc[0][2] += wv.x * x2; acc[0][3] += wv.x * x3;
            acc[1][0] += wv.y * x0; acc[1][1] += wv.y * x1; acc[1][2] += wv.y * x2; acc[1][3] += wv.y * x3;
            acc[2][0] += wv.z * x0; acc[2][1] += wv.z * x1; acc[2][2] += wv.z * x2; acc[2][3] += wv.z * x3;
            acc[3][0] += wv.w * x0; acc[3][1] += wv.w * x1; acc[3][2] += wv.w * x2; acc[3][3] += wv.w * x3;
        }
        __syncthreads();
    }
    #pragma unroll
    for (int i = 0; i < 4; i++) {
        int m = bm + tm * 4 + i;
        if (m >= M) continue;
        float bb = bias ? bias[m] : 0.f;
        #pragma unroll
        for (int j = 0; j < 4; j++) {
            int n = bn + tn * 4 + j;
            if (n >= N) continue;
            float v = acc[i][j] + bb;
            if (act == 1) v = tanhf(v);
            C[(long long)m * cm + (long long)n * cn] = v;
        }
    }
}

// ---------------- attention scores + softmax over batch (axis=1) ----------------
__global__ void scores_softmax_kernel(const float* __restrict__ hproj,
                                      const float* __restrict__ annproj,
                                      const float* __restrict__ w_a,
                                      float* __restrict__ attn,
                                      float* __restrict__ attns_out) {
    int s = blockIdx.x;             // 0..49
    int warp = threadIdx.x >> 5;
    int lane = threadIdx.x & 31;
    __shared__ float sm_scores[B];
    for (int it = 0; it < 4; it++) {
        int b = warp + it * 8;
        const float* ap = annproj + (size_t)(s * B + b) * H;
        const float* hp = hproj + (size_t)b * H;
        float sum = 0.f;
        for (int j = lane; j < H; j += 32)
            sum += tanhf(hp[j] + ap[j]) * w_a[j];
        #pragma unroll
        for (int o = 16; o > 0; o >>= 1) sum += __shfl_down_sync(0xffffffffu, sum, o);
        if (lane == 0) sm_scores[b] = sum;
    }
    __syncthreads();
    if (warp == 0) {
        float x = sm_scores[lane];
        float mx = x;
        #pragma unroll
        for (int o = 16; o > 0; o >>= 1) mx = fmaxf(mx, __shfl_xor_sync(0xffffffffu, mx, o));
        float e = expf(x - mx);
        float sum = e;
        #pragma unroll
        for (int o = 16; o > 0; o >>= 1) sum += __shfl_xor_sync(0xffffffffu, sum, o);
        float a = e / sum;
        attn[s * B + lane] = a;
        attns_out[s * B + lane] = a;
    }
}

// ---------------- build X slice: [emb(620), h_prev(1000), ctx(2000)] ----------------
__global__ void build_x_kernel(const int* __restrict__ tokens_t,     // tokens[t-1] base
                               const float* __restrict__ emb,
                               const float* __restrict__ h_prev,
                               const float* __restrict__ attn,
                               const float* __restrict__ ann,
                               float* __restrict__ Xslice) {
    int idx = blockIdx.x * blockDim.x + threadIdx.x;
    if (idx >= B * KX) return;
    int b = idx / KX;
    int e = idx % KX;
    float v;
    if (e < EMB) {
        int tok = tokens_t[b];
        v = emb[(size_t)tok * EMB + e];
    } else if (e < EMB + H) {
        v = h_prev[b * H + (e - EMB)];
    } else {
        int c = e - (EMB + H);
        float sum = 0.f;
        #pragma unroll 5
        for (int s = 0; s < S; s++)
            sum += attn[s * B + b] * ann[(size_t)(s * B + b) * A2 + c];
        v = sum;
    }
    Xslice[(size_t)b * KX + e] = v;
}

// ---------------- GRU combine ----------------
__global__ void gru_combine_kernel(const float* __restrict__ gates,   // [b][4000]
                                   const float* __restrict__ h_old,
                                   float* __restrict__ h_new,
                                   float* __restrict__ hid_out) {
    int idx = blockIdx.x * blockDim.x + threadIdx.x;
    if (idx >= B * H) return;
    int b = idx / H, j = idx % H;
    const float* g = gates + (size_t)b * 4000;
    float r  = 1.f / (1.f + expf(-g[j]));
    float z  = 1.f / (1.f + expf(-g[1000 + j]));
    float nn = tanhf(g[2000 + j] + r * g[3000 + j]);
    float hv = (1.f - z) * nn + z * h_old[idx];
    h_new[idx] = hv;
    if (hid_out) hid_out[idx] = hv;
}

// ---------------- zero preds[0] and attns[0] ----------------
__global__ void zero_kernel(float* __restrict__ out) {
    size_t idx = (size_t)blockIdx.x * blockDim.x + threadIdx.x;
    size_t n0 = (size_t)B * V;
    if (idx < n0) out[idx] = 0.f;
    else if (idx < n0 + S * B) out[ATT_OFF + (idx - n0)] = 0.f;
}

// ---------------- log-softmax in place, one block per (t,b) row ----------------
__global__ void logsoftmax_kernel(float* __restrict__ preds_base) {
    int row = blockIdx.x;            // 0..NPRED-1
    float* p = preds_base + (size_t)row * V;
    int tid = threadIdx.x;
    __shared__ float red[8];
    // max
    float mx = -1e30f;
    for (int i = tid; i < V; i += 256) mx = fmaxf(mx, p[i]);
    #pragma unroll
    for (int o = 16; o > 0; o >>= 1) mx = fmaxf(mx, __shfl_xor_sync(0xffffffffu, mx, o));
    if ((tid & 31) == 0) red[tid >> 5] = mx;
    __syncthreads();
    if (tid < 8) {
        float v = red[tid];
        #pragma unroll
        for (int o = 4; o > 0; o >>= 1) v = fmaxf(v, __shfl_xor_sync(0xffu, v, o));
        red[tid] = v;
    }
    __syncthreads();
    mx = red[0];
    __syncthreads();
    // sum exp
    float sum = 0.f;
    for (int i = tid; i < V; i += 256) sum += expf(p[i] - mx);
    #pragma unroll
    for (int o = 16; o > 0; o >>= 1) sum += __shfl_xor_sync(0xffffffffu, sum, o);
    if ((tid & 31) == 0) red[tid >> 5] = sum;
    __syncthreads();
    if (tid < 8) {
        float v = red[tid];
        #pragma unroll
        for (int o = 4; o > 0; o >>= 1) v += __shfl_xor_sync(0xffu, v, o);
        red[tid] = v;
    }
    __syncthreads();
    float lse = mx + logf(red[0]);
    for (int i = tid; i < V; i += 256) p[i] = p[i] - lse;
}

// ---------------- host orchestration ----------------
static inline int ceil_div(int a, int b) { return (a + b - 1) / b; }

extern "C" void kernel_launch(void* const* d_in, const int* in_sizes, int n_in,
                              void* d_out, int out_size) {
    const int*   tokens = (const int*)  d_in[0];
    const float* ann    = (const float*)d_in[1];
    const float* emb    = (const float*)d_in[2];
    const float* W_h    = (const float*)d_in[3];
    const float* b_h    = (const float*)d_in[4];
    const float* W_c    = (const float*)d_in[5];
    const float* b_c    = (const float*)d_in[6];
    const float* w_a    = (const float*)d_in[7];
    const float* W_ih   = (const float*)d_in[8];
    const float* W_hh   = (const float*)d_in[9];
    const float* b_ih   = (const float*)d_in[10];
    const float* b_hh   = (const float*)d_in[11];
    const float* W_p    = (const float*)d_in[12];
    const float* b_p    = (const float*)d_in[13];
    float* out = (float*)d_out;

    float* WhT; cudaGetSymbolAddress((void**)&WhT, g_WhT);
    float* WcT; cudaGetSymbolAddress((void**)&WcT, g_WcT);
    float* WpT; cudaGetSymbolAddress((void**)&WpT, g_WpT);
    float* WgT; cudaGetSymbolAddress((void**)&WgT, g_WgT);
    float* bg;  cudaGetSymbolAddress((void**)&bg,  g_bg);
    float* annproj; cudaGetSymbolAddress((void**)&annproj, g_annproj);
    float* hbuf; cudaGetSymbolAddress((void**)&hbuf, g_h);
    float* hproj; cudaGetSymbolAddress((void**)&hproj, g_hproj);
    float* attn; cudaGetSymbolAddress((void**)&attn, g_attn);
    float* Xall; cudaGetSymbolAddress((void**)&Xall, g_X);
    float* gates; cudaGetSymbolAddress((void**)&gates, g_gates);

    dim3 tb(32, 8);
    // transposes
    transpose_kernel<<<dim3(ceil_div(ECH, 32), ceil_div(H, 32)), tb>>>(W_h, WhT, H, ECH);
    transpose_kernel<<<dim3(ceil_div(H + A2, 32), ceil_div(H, 32)), tb>>>(W_c, WcT, H, H + A2);
    transpose_kernel<<<dim3(ceil_div(KX, 32), ceil_div(V, 32)), tb>>>(W_p, WpT, V, KX);
    {
        size_t total = (size_t)KX * 4000;
        build_wg_kernel<<<(int)((total + 255) / 256), 256>>>(W_ih, W_hh, WgT);
        build_bg_kernel<<<ceil_div(4000, 256), 256>>>(b_ih, b_hh, bg);
    }
    // zero preds[0], attns[0]
    {
        size_t total = (size_t)B * V + S * B;
        zero_kernel<<<(int)((total + 255) / 256), 256>>>(out);
    }
    // h0 = tanh(ann[0,:,ECH:] @ W_h^T + b_h)  -> g_h[0]
    gemm_kernel<<<dim3(ceil_div(H, 64), ceil_div(B, 32)), 128>>>(
        WhT, ann + ECH, b_h, hbuf, 1LL, (long long)H, H, B, ECH, H, A2, 1);
    // annproj = ann @ W_c[:,1000:]^T + b_c  -> [s*B+b][j]
    gemm_kernel<<<dim3(ceil_div(H, 64), ceil_div(S * B, 32)), 128>>>(
        WcT + (size_t)H * H, ann, b_c, annproj, 1LL, (long long)H, H, S * B, A2, H, A2, 0);

    int cur = 0;
    for (int t = 1; t <= NSTEP; t++) {
        int st = t - 1;
        float* h_cur = hbuf + (size_t)cur * B * H;
        float* h_nxt = hbuf + (size_t)(1 - cur) * B * H;
        float* Xs = Xall + (size_t)st * B * KX;

        // hproj = h @ W_c[:, :1000]^T
        gemm_kernel<<<dim3(ceil_div(H, 64), 1), 128>>>(
            WcT, h_cur, (const float*)nullptr, hproj, 1LL, (long long)H, H, B, H, H, H, 0);
        // scores + softmax over batch; also writes attns[t]
        scores_softmax_kernel<<<S, 256>>>(hproj, annproj, w_a, attn,
                                          out + ATT_OFF + (size_t)t * S * B);
        // build X slice (embed gather, h copy, context)
        build_x_kernel<<<ceil_div(B * KX, 256), 256>>>(
            tokens + (size_t)(t - 1) * B, emb, h_cur, attn, ann, Xs);
        // GRU gates GEMM -> gates[b][4000]
        gemm_kernel<<<dim3(ceil_div(4000, 64), 1), 128>>>(
            WgT, Xs, bg, gates, 1LL, 4000LL, 4000, B, KX, 4000, KX, 0);
        // combine -> h_nxt (and hidden output at final step)
        gru_combine_kernel<<<ceil_div(B * H, 256), 256>>>(
            gates, h_cur, h_nxt, (t == NSTEP) ? (out + HID_OFF) : (float*)nullptr);
        cur = 1 - cur;
    }

    // batched prediction logits for all steps -> preds[1..49], then log-softmax in place
    gemm_kernel<<<dim3(ceil_div(V, 64), ceil_div(NPRED, 32)), 128>>>(
        WpT, Xall, b_p, out + (size_t)B * V, 1LL, (long long)V, V, NPRED, KX, V, KX, 0);
    logsoftmax_kernel<<<NPRED, 256>>>(out + (size_t)B * V);
}